// round 2
// baseline (speedup 1.0000x reference)
#include <cuda_runtime.h>
#include <cuda_fp16.h>

#define T_STEPS 8192
#define IN_DIM  2048
#define MEM     2048
#define NCOL    10240   // 5*MEM
#define NCTA    148
#define NTHREADS 1024

// ---------------- device-global scratch (allowed: static, no runtime alloc) ----------------
__device__ __half g_Whh[(size_t)8192 * 2048];   // fp16 copy of Wh  (33.5 MB)
__device__ __half g_Wmh[(size_t)2048 * 2048];   // fp16 copy of Wm  ( 8.4 MB)
__device__ float  g_xg[(size_t)T_STEPS * NCOL]; // input projections (335 MB)
__device__ float  g_h[2][MEM];                  // double-buffered hidden state
__device__ float  g_m[MEM];                     // m = z * tanh(c)
__device__ unsigned int g_bar1;                 // monotonic barrier counters
__device__ unsigned int g_bar2;

// ---------------- init: reset state + barrier epochs every launch (graph-replay safe) -----
__global__ void k_init() {
    int i = blockIdx.x * blockDim.x + threadIdx.x;
    if (i == 0) { g_bar1 = 0u; g_bar2 = 0u; }
    if (i < MEM) { g_h[0][i] = 0.f; g_h[1][i] = 0.f; g_m[i] = 0.f; }
}

// ---------------- fp32 -> fp16 weight conversion -------------------------------------------
__global__ void k_convert(const float* __restrict__ Wh, const float* __restrict__ Wm) {
    const int n1 = 8192 * 2048;
    const int n2 = 2048 * 2048;
    int stride = gridDim.x * blockDim.x;
    for (int i = blockIdx.x * blockDim.x + threadIdx.x; i < n1; i += stride)
        g_Whh[i] = __float2half_rn(Wh[i]);
    for (int i = blockIdx.x * blockDim.x + threadIdx.x; i < n2; i += stride)
        g_Wmh[i] = __float2half_rn(Wm[i]);
}

// ---------------- GEMM: g_xg[T, 10240] = inputs[T,2048] @ Wx[10240,2048]^T + bx ------------
__global__ __launch_bounds__(256) void k_gemm(const float* __restrict__ A,
                                              const float* __restrict__ B,
                                              const float* __restrict__ bias) {
    __shared__ float As[16][128];
    __shared__ float Bs[16][128];
    const int bm = blockIdx.y * 128;
    const int bn = blockIdx.x * 128;
    const int tid = threadIdx.x;
    const int tx = tid & 15, ty = tid >> 4;

    float acc[8][8];
#pragma unroll
    for (int i = 0; i < 8; i++)
#pragma unroll
        for (int j = 0; j < 8; j++) acc[i][j] = 0.f;

    for (int k0 = 0; k0 < IN_DIM; k0 += 16) {
#pragma unroll
        for (int l = 0; l < 2; ++l) {
            int f4 = tid * 2 + l;             // 0..511
            int r  = f4 >> 2;                 // 0..127
            int cc = (f4 & 3) * 4;            // 0,4,8,12
            float4 v = *(const float4*)(A + (size_t)(bm + r) * IN_DIM + k0 + cc);
            As[cc + 0][r] = v.x; As[cc + 1][r] = v.y; As[cc + 2][r] = v.z; As[cc + 3][r] = v.w;
            float4 w = *(const float4*)(B + (size_t)(bn + r) * IN_DIM + k0 + cc);
            Bs[cc + 0][r] = w.x; Bs[cc + 1][r] = w.y; Bs[cc + 2][r] = w.z; Bs[cc + 3][r] = w.w;
        }
        __syncthreads();
#pragma unroll
        for (int k = 0; k < 16; ++k) {
            float a[8], b[8];
            *(float4*)&a[0] = *(const float4*)&As[k][ty * 8];
            *(float4*)&a[4] = *(const float4*)&As[k][ty * 8 + 4];
            *(float4*)&b[0] = *(const float4*)&Bs[k][tx * 8];
            *(float4*)&b[4] = *(const float4*)&Bs[k][tx * 8 + 4];
#pragma unroll
            for (int i = 0; i < 8; i++)
#pragma unroll
                for (int j = 0; j < 8; j++) acc[i][j] = fmaf(a[i], b[j], acc[i][j]);
        }
        __syncthreads();
    }
#pragma unroll
    for (int i = 0; i < 8; i++) {
        int m = bm + ty * 8 + i;
#pragma unroll
        for (int j = 0; j < 8; j += 4) {
            int n = bn + tx * 8 + j;
            float4 bv = *(const float4*)(bias + n);
            float4 o;
            o.x = acc[i][j + 0] + bv.x; o.y = acc[i][j + 1] + bv.y;
            o.z = acc[i][j + 2] + bv.z; o.w = acc[i][j + 3] + bv.w;
            *(float4*)(g_xg + (size_t)m * NCOL + n) = o;
        }
    }
}

// ---------------- barrier primitives (release/acquire, monotonic epochs) -------------------
__device__ __forceinline__ unsigned ld_acq(const unsigned* p) {
    unsigned v;
    asm volatile("ld.acquire.gpu.global.u32 %0, [%1];" : "=r"(v) : "l"(p) : "memory");
    return v;
}
__device__ __forceinline__ void red_rel(unsigned* p) {
    asm volatile("red.release.gpu.global.add.u32 [%0], 1;" :: "l"(p) : "memory");
}

// warp-cooperative dot of one fp16 weight row (2048) against SMEM-staged fp32 activations
__device__ __forceinline__ float warp_dot_h16(const __half* __restrict__ w,
                                              const float* sh, int lane) {
    float acc = 0.f;
    const uint2* wp = (const uint2*)w;  // 4 halves / 8B per lane: fully coalesced
#pragma unroll 4
    for (int it = 0; it < 16; ++it) {
        uint2 wv = __ldg(&wp[it * 32 + lane]);
        float4 hv = *(const float4*)(sh + it * 128 + lane * 4);  // conflict-free LDS.128
        __half2 w01 = *reinterpret_cast<__half2*>(&wv.x);
        __half2 w23 = *reinterpret_cast<__half2*>(&wv.y);
        float2 f01 = __half22float2(w01);
        float2 f23 = __half22float2(w23);
        acc = fmaf(f01.x, hv.x, acc);
        acc = fmaf(f01.y, hv.y, acc);
        acc = fmaf(f23.x, hv.z, acc);
        acc = fmaf(f23.y, hv.w, acc);
    }
#pragma unroll
    for (int o = 16; o > 0; o >>= 1) acc += __shfl_xor_sync(0xffffffffu, acc, o);
    return acc;
}

__device__ __forceinline__ float sigf(float x) { return 1.0f / (1.0f + __expf(-x)); }

// ---------------- persistent recurrent kernel ----------------------------------------------
__global__ __launch_bounds__(NTHREADS, 1) void k_recur(const float* __restrict__ bh,
                                                       const float* __restrict__ bmv,
                                                       float* __restrict__ out) {
    __shared__ float s_h[MEM];
    __shared__ float s_m[MEM];
    __shared__ float s_pre[14 * 4];
    __shared__ float s_c[14];

    const int b = blockIdx.x;
    const int tid = threadIdx.x;
    const int w = tid >> 5, lane = tid & 31;
    const int nu = (b < 124) ? 14 : 13;   // 2048 = 124*14 + 24*13, unit j -> CTA (j % 148)

    if (tid < nu) s_c[tid] = 0.f;
    __syncthreads();

    int cur = 0;
    for (int t = 0; t < T_STEPS; ++t) {
        const unsigned tgt = (unsigned)(t + 1) * NCTA;
        // stage h_old into SMEM
        for (int i = tid; i < MEM; i += NTHREADS) s_h[i] = g_h[cur][i];
        __syncthreads();
        const float* __restrict__ xg = g_xg + (size_t)t * NCOL;

        // ---- Phase A: z rows -> m ----
        if (w < nu) {
            int j = b + w * 148;
            float zacc = warp_dot_h16(g_Whh + (size_t)(4096 + j) * 2048, s_h, lane);
            if (lane == 0) {
                float z = sigf(zacc + bh[4096 + j] + xg[4096 + j]);
                g_m[j] = z * tanhf(s_c[w]);
            }
        }
        __syncthreads();
        if (tid == 0) red_rel(&g_bar1);   // publish m early; don't wait yet

        // ---- Phase B: i/o/f rows (independent of m -> hides barrier-1 latency) ----
        for (int d = w; d < 3 * nu; d += 32) {
            int g = d / nu;               // 0=i, 1=o, 2=f
            int r = d - g * nu;
            int row = ((g == 0) ? 0 : (g == 1) ? 2048 : 6144) + b + r * 148;
            float acc = warp_dot_h16(g_Whh + (size_t)row * 2048, s_h, lane);
            if (lane == 0) s_pre[r * 4 + g] = acc + bh[row];
        }

        if (tid == 0) { while (ld_acq(&g_bar1) < tgt) {} }
        __syncthreads();
        for (int i = tid; i < MEM; i += NTHREADS) s_m[i] = g_m[i];
        __syncthreads();

        // ---- Phase C: Wm@m + elementwise update ----
        if (w < nu) {
            int j = b + w * 148;
            float uacc = warp_dot_h16(g_Wmh + (size_t)j * 2048, s_m, lane);
            if (lane == 0) {
                float i_ = sigf(xg[j]        + s_pre[w * 4 + 0]);
                float o_ = sigf(xg[2048 + j] + s_pre[w * 4 + 1]);
                float f_ = sigf(xg[6144 + j] + s_pre[w * 4 + 2]);
                float u_ = tanhf(xg[8192 + j] + uacc + bmv[j]);
                float c  = i_ * u_ + f_ * s_c[w];
                s_c[w] = c;
                g_h[cur ^ 1][j] = o_ * tanhf(c);
            }
        }
        __syncthreads();
        if (tid == 0) { red_rel(&g_bar2); while (ld_acq(&g_bar2) < tgt) {} }
        __syncthreads();
        cur ^= 1;
    }

    if (b == 0) {
        for (int i = tid; i < MEM; i += NTHREADS) out[i] = g_h[cur][i];
    }
}

// ---------------- launch ---------------------------------------------------------------------
extern "C" void kernel_launch(void* const* d_in, const int* in_sizes, int n_in,
                              void* d_out, int out_size) {
    const float* inputs = (const float*)d_in[0];
    const float* Wx     = (const float*)d_in[1];
    const float* bx     = (const float*)d_in[2];
    const float* Wh     = (const float*)d_in[3];
    const float* bh     = (const float*)d_in[4];
    const float* Wm     = (const float*)d_in[5];
    const float* bm     = (const float*)d_in[6];
    float* out = (float*)d_out;

    k_init<<<8, 256>>>();
    k_convert<<<2048, 256>>>(Wh, Wm);
    k_gemm<<<dim3(NCOL / 128, T_STEPS / 128), 256>>>(inputs, Wx, bx);
    k_recur<<<NCTA, NTHREADS>>>(bh, bm, out);
}

// round 3
// speedup vs baseline: 1.2735x; 1.2735x over previous
#include <cuda_runtime.h>
#include <cuda_fp16.h>

#define T_STEPS 8192
#define IN_DIM  2048
#define MEM     2048
#define NCOL    10240   // 5*MEM
#define NCTA    148
#define NT      768     // 24 warps

// ---------------- device-global scratch ----------------
__device__ __align__(16) __half g_Whh[(size_t)8192 * 2048];  // fp16 Wh (33.5 MB)
__device__ __align__(16) __half g_Wmh[(size_t)2048 * 2048];  // fp16 Wm ( 8.4 MB)
__device__ float  g_xg[(size_t)T_STEPS * NCOL];              // input projections
__device__ __align__(16) float  g_h[2][MEM];                 // fp32 h (for output)
__device__ __align__(16) __half g_hh[2][MEM];                // fp16 h (for dots)
__device__ __align__(16) __half g_mh[MEM];                   // fp16 m
__device__ unsigned int g_bar1;
__device__ unsigned int g_bar2;

// ---------------- init (graph-replay safe) ----------------
__global__ void k_init() {
    int i = blockIdx.x * blockDim.x + threadIdx.x;
    if (i == 0) { g_bar1 = 0u; g_bar2 = 0u; }
    if (i < MEM) {
        g_h[0][i] = 0.f; g_h[1][i] = 0.f;
        g_hh[0][i] = __float2half_rn(0.f);
        g_hh[1][i] = __float2half_rn(0.f);
        g_mh[i]    = __float2half_rn(0.f);
    }
}

// ---------------- fp32 -> fp16 weights ----------------
__global__ void k_convert(const float* __restrict__ Wh, const float* __restrict__ Wm) {
    const int n1 = 8192 * 2048, n2 = 2048 * 2048;
    int stride = gridDim.x * blockDim.x;
    for (int i = blockIdx.x * blockDim.x + threadIdx.x; i < n1; i += stride)
        g_Whh[i] = __float2half_rn(Wh[i]);
    for (int i = blockIdx.x * blockDim.x + threadIdx.x; i < n2; i += stride)
        g_Wmh[i] = __float2half_rn(Wm[i]);
}

// ---------------- GEMM: g_xg = inputs @ Wx^T + bx (unchanged) ----------------
__global__ __launch_bounds__(256) void k_gemm(const float* __restrict__ A,
                                              const float* __restrict__ B,
                                              const float* __restrict__ bias) {
    __shared__ float As[16][128];
    __shared__ float Bs[16][128];
    const int bm = blockIdx.y * 128;
    const int bn = blockIdx.x * 128;
    const int tid = threadIdx.x;
    const int tx = tid & 15, ty = tid >> 4;
    float acc[8][8];
#pragma unroll
    for (int i = 0; i < 8; i++)
#pragma unroll
        for (int j = 0; j < 8; j++) acc[i][j] = 0.f;

    for (int k0 = 0; k0 < IN_DIM; k0 += 16) {
#pragma unroll
        for (int l = 0; l < 2; ++l) {
            int f4 = tid * 2 + l;
            int r  = f4 >> 2;
            int cc = (f4 & 3) * 4;
            float4 v = *(const float4*)(A + (size_t)(bm + r) * IN_DIM + k0 + cc);
            As[cc + 0][r] = v.x; As[cc + 1][r] = v.y; As[cc + 2][r] = v.z; As[cc + 3][r] = v.w;
            float4 w = *(const float4*)(B + (size_t)(bn + r) * IN_DIM + k0 + cc);
            Bs[cc + 0][r] = w.x; Bs[cc + 1][r] = w.y; Bs[cc + 2][r] = w.z; Bs[cc + 3][r] = w.w;
        }
        __syncthreads();
#pragma unroll
        for (int k = 0; k < 16; ++k) {
            float a[8], b[8];
            *(float4*)&a[0] = *(const float4*)&As[k][ty * 8];
            *(float4*)&a[4] = *(const float4*)&As[k][ty * 8 + 4];
            *(float4*)&b[0] = *(const float4*)&Bs[k][tx * 8];
            *(float4*)&b[4] = *(const float4*)&Bs[k][tx * 8 + 4];
#pragma unroll
            for (int i = 0; i < 8; i++)
#pragma unroll
                for (int j = 0; j < 8; j++) acc[i][j] = fmaf(a[i], b[j], acc[i][j]);
        }
        __syncthreads();
    }
#pragma unroll
    for (int i = 0; i < 8; i++) {
        int m = bm + ty * 8 + i;
#pragma unroll
        for (int j = 0; j < 8; j += 4) {
            int n = bn + tx * 8 + j;
            float4 bv = *(const float4*)(bias + n);
            float4 o;
            o.x = acc[i][j + 0] + bv.x; o.y = acc[i][j + 1] + bv.y;
            o.z = acc[i][j + 2] + bv.z; o.w = acc[i][j + 3] + bv.w;
            *(float4*)(g_xg + (size_t)m * NCOL + n) = o;
        }
    }
}

// ---------------- sync / math helpers ----------------
__device__ __forceinline__ unsigned ld_acq(const unsigned* p) {
    unsigned v;
    asm volatile("ld.acquire.gpu.global.u32 %0, [%1];" : "=r"(v) : "l"(p) : "memory");
    return v;
}
__device__ __forceinline__ void red_rel(unsigned* p) {
    asm volatile("red.release.gpu.global.add.u32 [%0], 1;" :: "l"(p) : "memory");
}
__device__ __forceinline__ float sigf(float x) { return 1.0f / (1.0f + __expf(-x)); }
__device__ __forceinline__ float wsum(float v) {
#pragma unroll
    for (int o = 16; o > 0; o >>= 1) v += __shfl_xor_sync(0xffffffffu, v, o);
    return v;
}
__device__ __forceinline__ __half2 h2u(unsigned u) { return *reinterpret_cast<__half2*>(&u); }

// 8 fp16 MACs: half2 partial (4 ops), flushed to two fp32 accumulators
__device__ __forceinline__ void mac8(uint4 wv, uint4 hv, float& ax, float& ay) {
    __half2 p = __hmul2(h2u(wv.x), h2u(hv.x));
    p = __hfma2(h2u(wv.y), h2u(hv.y), p);
    p = __hfma2(h2u(wv.z), h2u(hv.z), p);
    p = __hfma2(h2u(wv.w), h2u(hv.w), p);
    float2 f = __half22float2(p);
    ax += f.x; ay += f.y;
}

// ---------------- persistent recurrent kernel ----------------
#define DYN_SMEM (55 * 4096 + 4096)

__global__ __launch_bounds__(NT, 1) void k_recur(const float* __restrict__ bh,
                                                 const float* __restrict__ bmv,
                                                 float* __restrict__ out) {
    extern __shared__ __align__(16) unsigned char dyn[];
    __half* s_w  = (__half*)dyn;                       // 55 rows x 2048 fp16
    __half* s_hv = (__half*)(dyn + 55 * 4096);         // 2048 fp16 (h staged)
    __shared__ float s_pre[42];
    __shared__ volatile int s_flag;

    const int b = blockIdx.x;
    const int tid = threadIdx.x;
    const int w = tid >> 5, lane = tid & 31;
    const int nu = (b < 124) ? 14 : 13;                // units j = b + r*148, r<nu
    const int snu2 = 2 * nu;
    const int rows_tot = snu2 + 27;                    // z(nu) + Wm(nu) + 27 iof rows

    // ---- one-time: preload weight rows into SMEM ----
    for (int idx = tid; idx < rows_tot * 256; idx += NT) {
        int s = idx >> 8, col = idx & 255;
        const __half* src;
        if (s < nu)        src = g_Whh + (size_t)(4096 + b + s * 148) * 2048;
        else if (s < snu2) src = g_Wmh + (size_t)(b + (s - nu) * 148) * 2048;
        else {
            int d = s - snu2, g = d / nu, r = d - g * nu;
            int base = (g == 0) ? 0 : (g == 1) ? 2048 : 6144;
            src = g_Whh + (size_t)(base + b + r * 148) * 2048;
        }
        ((uint4*)s_w)[idx] = ((const uint4*)src)[col];
    }
    if (tid == 0) s_flag = 0;

    // ---- per-warp persistent setup ----
    int r0 = 0, j0 = 0, j1 = 0;
    bool v1 = false;
    const uint4 *pz0 = 0, *pz1 = 0, *pm0 = 0, *pm1 = 0;
    float bhz0 = 0.f, bhz1 = 0.f, bm0 = 0.f, bm1 = 0.f;
    float c0 = 0.f, c1 = 0.f;

    bool bact = false, bsm = false;
    int d0 = 0;
    const uint4 *q0 = 0, *q1 = 0, *q2 = 0;
    float bhb0 = 0.f, bhb1 = 0.f, bhb2 = 0.f;

    if (w < 7) {
        r0 = 2 * w;
        v1 = (2 * w + 1) < nu;
        int r1 = v1 ? (2 * w + 1) : r0;
        j0 = b + r0 * 148; j1 = b + r1 * 148;
        pz0 = (const uint4*)(s_w + (size_t)r0 * 2048);
        pz1 = (const uint4*)(s_w + (size_t)r1 * 2048);
        pm0 = (const uint4*)(s_w + (size_t)(nu + r0) * 2048);
        pm1 = (const uint4*)(s_w + (size_t)(nu + r1) * 2048);
        bhz0 = bh[4096 + j0]; bhz1 = bh[4096 + j1];
        bm0 = bmv[j0]; bm1 = bmv[j1];
    } else if (w < 21) {
        int wb = w - 7;
        bact = wb < nu;
        d0 = 3 * wb;
        bsm = (d0 < 27);
        if (bact) {
            int row[3];
#pragma unroll
            for (int k = 0; k < 3; k++) {
                int d = d0 + k, g = d / nu, r = d - g * nu;
                row[k] = ((g == 0) ? 0 : (g == 1) ? 2048 : 6144) + b + r * 148;
            }
            bhb0 = bh[row[0]]; bhb1 = bh[row[1]]; bhb2 = bh[row[2]];
            if (bsm) {
                q0 = (const uint4*)(s_w + (size_t)(snu2 + d0 + 0) * 2048);
                q1 = (const uint4*)(s_w + (size_t)(snu2 + d0 + 1) * 2048);
                q2 = (const uint4*)(s_w + (size_t)(snu2 + d0 + 2) * 2048);
            } else {
                q0 = (const uint4*)(g_Whh + (size_t)row[0] * 2048);
                q1 = (const uint4*)(g_Whh + (size_t)row[1] * 2048);
                q2 = (const uint4*)(g_Whh + (size_t)row[2] * 2048);
            }
        }
    }
    __syncthreads();

    int cur = 0;
    for (int t = 0; t < T_STEPS; ++t) {
        // wait for all h(t-1) writes, then stage h into SMEM
        if (tid == 0 && t) { while (ld_acq(&g_bar2) < (unsigned)t * 1036u) {} }
        __syncthreads();
        {
            const unsigned* src = (const unsigned*)g_hh[cur];
            unsigned* dst = (unsigned*)s_hv;
            dst[tid] = src[tid];
            if (tid < 256) dst[NT + tid] = src[NT + tid];
        }
        __syncthreads();

        const float* __restrict__ xg = g_xg + (size_t)t * NCOL;
        const uint4* hh = (const uint4*)s_hv;

        float ix0, ix1, ox0, ox1, fx0, fx1, ux0, ux1, u0 = 0.f, u1 = 0.f;

        if (w < 7) {
            // xg prefetch (broadcast loads, latency hidden by z-dot)
            float zx0 = __ldg(xg + 4096 + j0);
            float zx1 = __ldg(xg + 4096 + j1);
            ix0 = __ldg(xg + j0);        ix1 = __ldg(xg + j1);
            ox0 = __ldg(xg + 2048 + j0); ox1 = __ldg(xg + 2048 + j1);
            fx0 = __ldg(xg + 6144 + j0); fx1 = __ldg(xg + 6144 + j1);
            ux0 = __ldg(xg + 8192 + j0); ux1 = __ldg(xg + 8192 + j1);

            // ---- Phase A: z rows (SMEM weights + SMEM h) ----
            float a0x = 0.f, a0y = 0.f, a1x = 0.f, a1y = 0.f;
#pragma unroll
            for (int i = 0; i < 8; i++) {
                uint4 hv = hh[i * 32 + lane];
                mac8(pz0[i * 32 + lane], hv, a0x, a0y);
                mac8(pz1[i * 32 + lane], hv, a1x, a1y);
            }
            float z0 = wsum(a0x + a0y);
            float z1 = wsum(a1x + a1y);
            float m0 = sigf(z0 + bhz0 + zx0) * tanhf(c0);
            float m1 = sigf(z1 + bhz1 + zx1) * tanhf(c1);
            if (lane == 0) {
                g_mh[j0] = __float2half_rn(m0);
                if (v1) g_mh[j1] = __float2half_rn(m1);
                red_rel(&g_bar1);
            }
            // warp 0 polls global bar1; others spin on SMEM flag
            if (w == 0) {
                if (lane == 0) {
                    while (ld_acq(&g_bar1) < (unsigned)(t + 1) * 1036u) {}
                    __threadfence_block();
                    s_flag = t + 1;
                }
                __syncwarp();
            } else {
                if (lane == 0) { while (s_flag < t + 1) {} }
                __syncwarp();
                __threadfence_block();
            }
            // ---- Phase C dot: Wm rows (SMEM weights, m from L2) ----
            const uint4* gm = (const uint4*)g_mh;
            float b0x = 0.f, b0y = 0.f, b1x = 0.f, b1y = 0.f;
#pragma unroll
            for (int i = 0; i < 8; i++) {
                uint4 mv = __ldg(&gm[i * 32 + lane]);
                mac8(pm0[i * 32 + lane], mv, b0x, b0y);
                mac8(pm1[i * 32 + lane], mv, b1x, b1y);
            }
            u0 = wsum(b0x + b0y);
            u1 = wsum(b1x + b1y);
        } else if (bact) {
            // ---- Phase B: i/o/f rows (3 per warp; SMEM or L2 weights) ----
            float s0x = 0.f, s0y = 0.f, s1x = 0.f, s1y = 0.f, s2x = 0.f, s2y = 0.f;
            if (bsm) {
#pragma unroll
                for (int i = 0; i < 8; i++) {
                    uint4 hv = hh[i * 32 + lane];
                    mac8(q0[i * 32 + lane], hv, s0x, s0y);
                    mac8(q1[i * 32 + lane], hv, s1x, s1y);
                    mac8(q2[i * 32 + lane], hv, s2x, s2y);
                }
            } else {
#pragma unroll
                for (int i = 0; i < 8; i++) {
                    uint4 hv = hh[i * 32 + lane];
                    mac8(__ldg(&q0[i * 32 + lane]), hv, s0x, s0y);
                    mac8(__ldg(&q1[i * 32 + lane]), hv, s1x, s1y);
                    mac8(__ldg(&q2[i * 32 + lane]), hv, s2x, s2y);
                }
            }
            float p0 = wsum(s0x + s0y);
            float p1 = wsum(s1x + s1y);
            float p2 = wsum(s2x + s2y);
            if (lane == 0) {
                s_pre[d0 + 0] = p0 + bhb0;
                s_pre[d0 + 1] = p1 + bhb1;
                s_pre[d0 + 2] = p2 + bhb2;
            }
        }
        __syncthreads();   // s_pre ready

        if (w < 7) {
            // ---- Phase C final: gates + cell update ----
            float i0 = sigf(ix0 + s_pre[r0]);
            float o0 = sigf(ox0 + s_pre[nu + r0]);
            float f0 = sigf(fx0 + s_pre[2 * nu + r0]);
            float uu0 = tanhf(ux0 + u0 + bm0);
            c0 = i0 * uu0 + f0 * c0;
            float hn0 = o0 * tanhf(c0);
            float hn1 = 0.f;
            if (v1) {
                int r1 = r0 + 1;
                float i1 = sigf(ix1 + s_pre[r1]);
                float o1 = sigf(ox1 + s_pre[nu + r1]);
                float f1 = sigf(fx1 + s_pre[2 * nu + r1]);
                float uu1 = tanhf(ux1 + u1 + bm1);
                c1 = i1 * uu1 + f1 * c1;
                hn1 = o1 * tanhf(c1);
            }
            if (lane == 0) {
                int nxt = cur ^ 1;
                g_h[nxt][j0]  = hn0;
                g_hh[nxt][j0] = __float2half_rn(hn0);
                if (v1) {
                    g_h[nxt][j1]  = hn1;
                    g_hh[nxt][j1] = __float2half_rn(hn1);
                }
                red_rel(&g_bar2);
            }
        }
        cur ^= 1;
    }

    // ---- output: h_T (CTA 0 copies after all final writes land) ----
    if (b == 0) {
        if (tid == 0) { while (ld_acq(&g_bar2) < 1036u * (unsigned)T_STEPS) {} }
        __syncthreads();
        for (int i = tid; i < MEM; i += NT) out[i] = g_h[cur][i];
    }
}

// ---------------- launch ----------------
extern "C" void kernel_launch(void* const* d_in, const int* in_sizes, int n_in,
                              void* d_out, int out_size) {
    const float* inputs = (const float*)d_in[0];
    const float* Wx     = (const float*)d_in[1];
    const float* bx     = (const float*)d_in[2];
    const float* Wh     = (const float*)d_in[3];
    const float* bh     = (const float*)d_in[4];
    const float* Wm     = (const float*)d_in[5];
    const float* bm     = (const float*)d_in[6];
    float* out = (float*)d_out;

    cudaFuncSetAttribute(k_recur, cudaFuncAttributeMaxDynamicSharedMemorySize, DYN_SMEM);

    k_init<<<8, 256>>>();
    k_convert<<<2048, 256>>>(Wh, Wm);
    k_gemm<<<dim3(NCOL / 128, T_STEPS / 128), 256>>>(inputs, Wx, bx);
    k_recur<<<NCTA, NT, DYN_SMEM>>>(bh, bm, out);
}